// round 5
// baseline (speedup 1.0000x reference)
#include <cuda_runtime.h>
#include <cstdint>
#include <cstddef>

#define HH 128
#define WW 128
#define HW 16384
#define CC 192
#define C3 576
#define BB 8
#define NHEADS 4
#define CH 48
#define GK 192   // K dim of both big GEMMs

// ---------------- scratch (static device globals; no allocation in kernel_launch) ----
__device__ float g_mask[BB * HW];                         // [b, hw] single-channel mask
__device__ float g_qkv [(size_t)BB * C3 * HW];            // after 1x1 conv
__device__ float g_qkvd[(size_t)BB * C3 * HW];            // after dwconv (+mask on q,k)
__device__ float g_ssp [BB * 2 * CC * HH];                // sumsq partials per image row
__device__ float g_sumsq[BB * 2 * CC];                    // ||q_c||^2, ||k_c||^2
__device__ float g_Spart[(size_t)32 * BB * NHEADS * CH * CH]; // QK^T partials per k-chunk
__device__ float g_S [BB * NHEADS * CH * CH];             // QK^T
__device__ float g_M [BB * CC * CC];                      // proj_w folded with attn

// ---------------- packed f32x2 helpers (Blackwell) -----------------------------------
__device__ __forceinline__ unsigned long long fma2(unsigned long long a,
                                                   unsigned long long b,
                                                   unsigned long long c) {
    unsigned long long d;
    asm("fma.rn.f32x2 %0, %1, %2, %3;" : "=l"(d) : "l"(a), "l"(b), "l"(c));
    return d;
}
__device__ __forceinline__ unsigned long long pack2(float lo, float hi) {
    unsigned long long d;
    asm("mov.b64 %0, {%1, %2};" : "=l"(d) : "f"(lo), "f"(hi));
    return d;
}
__device__ __forceinline__ float2 unpack2(unsigned long long v) {
    float2 r;
    asm("mov.b64 {%0, %1}, %2;" : "=f"(r.x), "=f"(r.y) : "l"(v));
    return r;
}

// ---------------- K1: mask_single[b,p] = sum_c [(Input-x) > thr] * cm_w[c] -----------
__global__ void __launch_bounds__(256) mask_kernel(
    const float* __restrict__ x, const float* __restrict__ inp,
    const float* __restrict__ cmw, const float* __restrict__ thr_p,
    float* __restrict__ mask)
{
    __shared__ float cw[CC];
    int t = threadIdx.x;
    if (t < CC) cw[t] = cmw[t];
    __syncthreads();
    float thr = *thr_p;
    int p = blockIdx.x * 256 + t;
    int b = blockIdx.y;
    size_t off = (size_t)b * CC * HW + p;
    float acc = 0.f;
#pragma unroll 4
    for (int c = 0; c < CC; c++) {
        float d = inp[off + (size_t)c * HW] - x[off + (size_t)c * HW];
        acc += (d > thr) ? cw[c] : 0.f;
    }
    mask[(size_t)b * HW + p] = acc;
}

// ---------------- SGEMM: C[M,16384] = A[M,192] * B[192,16384], batched over z ---------
// BM=BN=128, BK=16, 256 threads, 8x8 per thread, f32x2 packed along M pairs.
__global__ void __launch_bounds__(256) sgemm192(
    const float* __restrict__ A, const float* __restrict__ B, float* __restrict__ C,
    int M, size_t sA, size_t sB, size_t sC)
{
    const int N = HW;
    A += (size_t)blockIdx.z * sA;
    B += (size_t)blockIdx.z * sB;
    C += (size_t)blockIdx.z * sC;
    __shared__ float As[16][128];   // [k][m]
    __shared__ float Bs[16][128];   // [k][n]
    int tid = threadIdx.x;
    int m0 = blockIdx.y * 128;
    int n0 = blockIdx.x * 128;
    int ar = tid >> 1;              // A tile row 0..127
    int ah = (tid & 1) << 3;        // A k-half 0/8
    int br = tid >> 5;              // B tile row 0..7 (and +8)
    int bc = (tid & 31) << 2;       // B tile col (float4)
    int tm = (tid >> 4) << 3;       // per-thread m base
    int tn = (tid & 15) << 3;       // per-thread n base

    unsigned long long acc[4][8];
#pragma unroll
    for (int i = 0; i < 4; i++)
#pragma unroll
        for (int j = 0; j < 8; j++) acc[i][j] = 0ULL;

    for (int kt = 0; kt < GK; kt += 16) {
        float4 a0, a1;
        int gm = m0 + ar;
        if (gm < M) {
            const float4* ap = (const float4*)(A + (size_t)gm * GK + kt + ah);
            a0 = ap[0]; a1 = ap[1];
        } else {
            a0 = make_float4(0.f, 0.f, 0.f, 0.f); a1 = a0;
        }
        float4 b0 = *(const float4*)(B + (size_t)(kt + br) * N + n0 + bc);
        float4 b1 = *(const float4*)(B + (size_t)(kt + br + 8) * N + n0 + bc);
        __syncthreads();
        As[ah + 0][ar] = a0.x; As[ah + 1][ar] = a0.y;
        As[ah + 2][ar] = a0.z; As[ah + 3][ar] = a0.w;
        As[ah + 4][ar] = a1.x; As[ah + 5][ar] = a1.y;
        As[ah + 6][ar] = a1.z; As[ah + 7][ar] = a1.w;
        *(float4*)&Bs[br][bc] = b0;
        *(float4*)&Bs[br + 8][bc] = b1;
        __syncthreads();
#pragma unroll
        for (int kk = 0; kk < 16; kk++) {
            const unsigned long long* ap2 =
                (const unsigned long long*)&As[kk][tm];
            unsigned long long a2[4];
#pragma unroll
            for (int i = 0; i < 4; i++) a2[i] = ap2[i];
            float4 bb0 = *(const float4*)&Bs[kk][tn];
            float4 bb1 = *(const float4*)&Bs[kk][tn + 4];
            unsigned long long bp[8];
            bp[0] = pack2(bb0.x, bb0.x); bp[1] = pack2(bb0.y, bb0.y);
            bp[2] = pack2(bb0.z, bb0.z); bp[3] = pack2(bb0.w, bb0.w);
            bp[4] = pack2(bb1.x, bb1.x); bp[5] = pack2(bb1.y, bb1.y);
            bp[6] = pack2(bb1.z, bb1.z); bp[7] = pack2(bb1.w, bb1.w);
#pragma unroll
            for (int i = 0; i < 4; i++)
#pragma unroll
                for (int j = 0; j < 8; j++)
                    acc[i][j] = fma2(a2[i], bp[j], acc[i][j]);
        }
    }
#pragma unroll
    for (int i = 0; i < 4; i++) {
        int row0 = m0 + tm + 2 * i;     // M is even, row pairs share validity
        if (row0 >= M) continue;
        float2 f[8];
#pragma unroll
        for (int j = 0; j < 8; j++) f[j] = unpack2(acc[i][j]);
        float4 lo0 = make_float4(f[0].x, f[1].x, f[2].x, f[3].x);
        float4 lo1 = make_float4(f[4].x, f[5].x, f[6].x, f[7].x);
        float4 hi0 = make_float4(f[0].y, f[1].y, f[2].y, f[3].y);
        float4 hi1 = make_float4(f[4].y, f[5].y, f[6].y, f[7].y);
        float* cp0 = C + (size_t)row0 * N + n0 + tn;
        *(float4*)cp0 = lo0; *(float4*)(cp0 + 4) = lo1;
        float* cp1 = cp0 + N;
        *(float4*)cp1 = hi0; *(float4*)(cp1 + 4) = hi1;
    }
}

// ---------------- K3: depthwise 3x3 + mask on q,k + sumsq partials -------------------
__global__ void __launch_bounds__(128) dw_kernel(
    const float* __restrict__ in, const float* __restrict__ dww,
    const float* __restrict__ mask, float* __restrict__ out,
    float* __restrict__ ssp)
{
    int xx = threadIdx.x;
    int y  = blockIdx.x;
    int oc = blockIdx.y;
    int b  = blockIdx.z;
    size_t base = ((size_t)b * C3 + oc) * HW;
    float w[9];
#pragma unroll
    for (int i = 0; i < 9; i++) w[i] = __ldg(&dww[oc * 9 + i]);
    float acc = 0.f;
#pragma unroll
    for (int ky = -1; ky <= 1; ky++) {
        int yy = y + ky;
        if (yy < 0 || yy >= HH) continue;
        const float* rp = in + base + (size_t)yy * WW;
#pragma unroll
        for (int kx = -1; kx <= 1; kx++) {
            int xp = xx + kx;
            if (xp < 0 || xp >= WW) continue;
            acc += rp[xp] * w[(ky + 1) * 3 + (kx + 1)];
        }
    }
    int pix = y * WW + xx;
    __shared__ float red[4];
    if (oc < 2 * CC) {   // q or k channel: apply mask, collect sumsq
        acc *= mask[(size_t)b * HW + pix];
        float s = acc * acc;
#pragma unroll
        for (int off = 16; off; off >>= 1)
            s += __shfl_down_sync(0xffffffffu, s, off);
        if ((xx & 31) == 0) red[xx >> 5] = s;
        __syncthreads();
        if (xx == 0)
            ssp[(size_t)(b * 2 * CC + oc) * HH + y] =
                red[0] + red[1] + red[2] + red[3];
    }
    out[base + pix] = acc;
}

// ---------------- K3b: reduce sumsq partials (128 rows -> 1) -------------------------
__global__ void __launch_bounds__(128) ssreduce_kernel(
    const float* __restrict__ part, float* __restrict__ sumsq)
{
    int id = blockIdx.x;     // b*384 + oc
    int t  = threadIdx.x;
    float v = part[(size_t)id * HH + t];
#pragma unroll
    for (int off = 16; off; off >>= 1)
        v += __shfl_down_sync(0xffffffffu, v, off);
    __shared__ float red[4];
    if ((t & 31) == 0) red[t >> 5] = v;
    __syncthreads();
    if (t == 0) sumsq[id] = red[0] + red[1] + red[2] + red[3];
}

// ---------------- K4: S[b,h] += Q[b,h] K[b,h]^T over a 512-pixel chunk ----------------
// 64 threads (8x8), 6x6 micro-tile per thread, f32x2 over pixel pairs.
__global__ void __launch_bounds__(64) qk_kernel(
    const float* __restrict__ qk, float* __restrict__ Spart)
{
    int chunk = blockIdx.x;      // 0..31
    int h = blockIdx.y;
    int b = blockIdx.z;
    const float* qbase = qk + ((size_t)b * C3 + h * CH) * HW;
    const float* kbase = qk + ((size_t)b * C3 + CC + h * CH) * HW;
    int p0 = chunk * 512;
    __shared__ float qs[CH][34];   // pad 34: even (f32x2-aligned) + conflict-free
    __shared__ float ks[CH][34];
    int t  = threadIdx.x;
    int ti = t >> 3, tj = t & 7;
    unsigned long long acc[6][6];
#pragma unroll
    for (int i = 0; i < 6; i++)
#pragma unroll
        for (int j = 0; j < 6; j++) acc[i][j] = 0ULL;

    for (int sub = 0; sub < 16; sub++) {
        int pp = p0 + sub * 32;
        __syncthreads();
#pragma unroll
        for (int j = 0; j < 6; j++) {
            int id = t + j * 64;             // 0..383
            int row = id >> 3;
            int c4  = (id & 7) * 4;
            float4 v = *(const float4*)(qbase + (size_t)row * HW + pp + c4);
            qs[row][c4] = v.x; qs[row][c4 + 1] = v.y;
            qs[row][c4 + 2] = v.z; qs[row][c4 + 3] = v.w;
            float4 w = *(const float4*)(kbase + (size_t)row * HW + pp + c4);
            ks[row][c4] = w.x; ks[row][c4 + 1] = w.y;
            ks[row][c4 + 2] = w.z; ks[row][c4 + 3] = w.w;
        }
        __syncthreads();
#pragma unroll
        for (int kk = 0; kk < 16; kk++) {
            unsigned long long q2[6], k2[6];
#pragma unroll
            for (int i = 0; i < 6; i++)
                q2[i] = *(const unsigned long long*)&qs[ti * 6 + i][kk * 2];
#pragma unroll
            for (int j = 0; j < 6; j++)
                k2[j] = *(const unsigned long long*)&ks[tj * 6 + j][kk * 2];
#pragma unroll
            for (int i = 0; i < 6; i++)
#pragma unroll
                for (int j = 0; j < 6; j++)
                    acc[i][j] = fma2(q2[i], k2[j], acc[i][j]);
        }
    }
    float* Sp = Spart + (size_t)chunk * (BB * NHEADS * CH * CH)
                      + (size_t)(b * NHEADS + h) * (CH * CH);
#pragma unroll
    for (int i = 0; i < 6; i++)
#pragma unroll
        for (int j = 0; j < 6; j++) {
            float2 f = unpack2(acc[i][j]);
            Sp[(ti * 6 + i) * CH + tj * 6 + j] = f.x + f.y;
        }
}

// ---------------- K4b: reduce S partials over 32 chunks ------------------------------
__global__ void __launch_bounds__(256) sreduce_kernel(
    const float* __restrict__ part, float* __restrict__ S)
{
    int i = blockIdx.x * 256 + threadIdx.x;   // < 73728
    float s = 0.f;
#pragma unroll
    for (int c = 0; c < 32; c++)
        s += part[(size_t)c * (BB * NHEADS * CH * CH) + i];
    S[i] = s;
}

// ---------------- K5: cosine-scale + softmax + fold proj into M ----------------------
__global__ void __launch_bounds__(256) attn_kernel(
    const float* __restrict__ S, const float* __restrict__ sumsq,
    const float* __restrict__ temp, const float* __restrict__ projw,
    float* __restrict__ Mout)
{
    int h = blockIdx.x, b = blockIdx.y;
    __shared__ float att[CH][CH];
    __shared__ float rnq[CH], rnk[CH];
    int t = threadIdx.x;
    if (t < CH) {
        float nq = sqrtf(sumsq[b * 2 * CC + h * CH + t]);
        float nk = sqrtf(sumsq[b * 2 * CC + CC + h * CH + t]);
        rnq[t] = 1.f / fmaxf(nq, 1e-12f);
        rnk[t] = 1.f / fmaxf(nk, 1e-12f);
    }
    __syncthreads();
    float T = temp[h];
    const float* Sp = S + (size_t)(b * NHEADS + h) * (CH * CH);
    for (int i = t; i < CH * CH; i += 256) {
        int c = i / CH, d = i % CH;
        att[c][d] = Sp[i] * rnq[c] * rnk[d] * T;
    }
    __syncthreads();
    if (t < CH) {          // softmax over d, one thread per row
        float mx = -1e30f;
#pragma unroll
        for (int d = 0; d < CH; d++) mx = fmaxf(mx, att[t][d]);
        float sum = 0.f;
#pragma unroll
        for (int d = 0; d < CH; d++) {
            float e = expf(att[t][d] - mx);
            att[t][d] = e;
            sum += e;
        }
        float inv = 1.f / sum;
#pragma unroll
        for (int d = 0; d < CH; d++) att[t][d] *= inv;
    }
    __syncthreads();
    // M[o, h*48+d] = sum_c proj_w[o, h*48+c] * att[c][d]
    for (int i = t; i < CC * CH; i += 256) {
        int o = i / CH, d = i % CH;
        float s = 0.f;
#pragma unroll
        for (int c = 0; c < CH; c++)
            s += projw[o * CC + h * CH + c] * att[c][d];
        Mout[((size_t)b * CC + o) * CC + h * CH + d] = s;
    }
}

// ---------------- launch --------------------------------------------------------------
extern "C" void kernel_launch(void* const* d_in, const int* in_sizes, int n_in,
                              void* d_out, int out_size)
{
    const float* x     = (const float*)d_in[0];
    const float* inp   = (const float*)d_in[1];
    const float* qkvw  = (const float*)d_in[2];
    const float* dww   = (const float*)d_in[3];
    const float* projw = (const float*)d_in[4];
    const float* cmw   = (const float*)d_in[5];
    const float* temp  = (const float*)d_in[6];
    const float* thr   = (const float*)d_in[7];
    float* out = (float*)d_out;

    float *p_mask, *p_qkv, *p_qkvd, *p_ssp, *p_sumsq, *p_spart, *p_S, *p_M;
    cudaGetSymbolAddress((void**)&p_mask,  g_mask);
    cudaGetSymbolAddress((void**)&p_qkv,   g_qkv);
    cudaGetSymbolAddress((void**)&p_qkvd,  g_qkvd);
    cudaGetSymbolAddress((void**)&p_ssp,   g_ssp);
    cudaGetSymbolAddress((void**)&p_sumsq, g_sumsq);
    cudaGetSymbolAddress((void**)&p_spart, g_Spart);
    cudaGetSymbolAddress((void**)&p_S,     g_S);
    cudaGetSymbolAddress((void**)&p_M,     g_M);

    // K1: single-channel mask
    mask_kernel<<<dim3(HW / 256, BB), 256>>>(x, inp, cmw, thr, p_mask);
    // K2: qkv 1x1 conv  (C3 x HW per batch)
    sgemm192<<<dim3(HW / 128, (C3 + 127) / 128, BB), 256>>>(
        qkvw, x, p_qkv, C3, (size_t)0, (size_t)CC * HW, (size_t)C3 * HW);
    // K3: depthwise 3x3 + mask + sumsq partials
    dw_kernel<<<dim3(HH, C3, BB), 128>>>(p_qkv, dww, p_mask, p_qkvd, p_ssp);
    // K3b: sumsq reduce
    ssreduce_kernel<<<BB * 2 * CC, 128>>>(p_ssp, p_sumsq);
    // K4: S = Q K^T partials over 32 pixel-chunks
    qk_kernel<<<dim3(32, NHEADS, BB), 64>>>(p_qkvd, p_spart);
    // K4b: S reduce
    sreduce_kernel<<<(BB * NHEADS * CH * CH) / 256, 256>>>(p_spart, p_S);
    // K5: scale + softmax + fold proj into M
    attn_kernel<<<dim3(NHEADS, BB), 256>>>(p_S, p_sumsq, temp, projw, p_M);
    // K6: out = M @ v   (v = channels 384..575 of g_qkvd)
    sgemm192<<<dim3(HW / 128, (CC + 127) / 128, BB), 256>>>(
        p_M, p_qkvd + (size_t)2 * CC * HW, out, CC,
        (size_t)CC * CC, (size_t)C3 * HW, (size_t)CC * HW);
}